// round 9
// baseline (speedup 1.0000x reference)
#include <cuda_runtime.h>
#include <cstdint>

// Problem constants
#define NB 2
#define NS 2048
#define ND 1024
#define NH 16
#define NHD 64
#define NM (NB*NS)
#define SCALE_F 0.125f      // 64^-0.5

// Scratch (alloc-free rule: __device__ globals)
__device__ float g_q[NB*NH*NS*NHD];
__device__ float g_k[NB*NH*NS*NHD];
__device__ float g_v[NB*NH*NS*NHD];
__device__ float g_att[NB*NS*ND];

// ---------------------------------------------------------------------------
__device__ __forceinline__ uint32_t cvt_tf32(float f) {
    uint32_t r;
    asm("cvt.rna.tf32.f32 %0, %1;" : "=r"(r) : "f"(f));
    return r;
}

__device__ __forceinline__ void mma_tf32(float c[4],
                                         uint32_t a0, uint32_t a1,
                                         uint32_t a2, uint32_t a3,
                                         uint32_t b0, uint32_t b1) {
    asm volatile(
        "mma.sync.aligned.m16n8k8.row.col.f32.tf32.tf32.f32 "
        "{%0,%1,%2,%3}, {%4,%5,%6,%7}, {%8,%9}, {%0,%1,%2,%3};"
        : "+f"(c[0]), "+f"(c[1]), "+f"(c[2]), "+f"(c[3])
        : "r"(a0), "r"(a1), "r"(a2), "r"(a3), "r"(b0), "r"(b1));
}

// ---------------------------------------------------------------------------
// Double-buffered tf32 mma.sync GEMM, fused multi-output.
// grid.z selects (W, bias, C) triple. CTA 128x128, BK=32, one sync per chunk.
// Dynamic smem: 2 stages x (sA + sB) = 2*2*128*36*4 = 73728 B.
// SCATTER=true writes [B,H,S,HD] (fused head-split transpose).
// ---------------------------------------------------------------------------
#define SSTR 36
#define GEMM_SMEM_BYTES (2 * 2 * 128 * SSTR * 4)

template<bool SCATTER>
__global__ void __launch_bounds__(256)
gemm_db(const float* __restrict__ A,
        const float* __restrict__ W0, const float* __restrict__ b0, float* __restrict__ C0,
        const float* __restrict__ W1, const float* __restrict__ b1, float* __restrict__ C1,
        const float* __restrict__ W2, const float* __restrict__ b2, float* __restrict__ C2)
{
    constexpr int N = ND, K = ND;
    constexpr int BK = 32;
    constexpr int NCHUNK = K / BK;   // 32

    extern __shared__ uint32_t gsm[];
    uint32_t* stA[2] = { gsm,                 gsm + 2*128*SSTR };
    uint32_t* stB[2] = { gsm + 128*SSTR,      gsm + 3*128*SSTR };

    const float* W;
    const float* bias;
    float* C;
    if (blockIdx.z == 0)      { W = W0; bias = b0; C = C0; }
    else if (blockIdx.z == 1) { W = W1; bias = b1; C = C1; }
    else                      { W = W2; bias = b2; C = C2; }

    const int tid  = threadIdx.x;
    const int wid  = tid >> 5;
    const int lane = tid & 31;
    const int m0   = blockIdx.y * 128;
    const int n0   = blockIdx.x * 128;

    const int wm = (wid >> 2) * 64;
    const int wn = (wid & 3)  * 32;

    const int nloc = tid & 127;
    const int kb   = (tid >> 7) * 16;

    // gmem->reg prefetch
    const int arow = tid >> 1;           // 0..127 (2 float4 per row pair)
    const int acol = (tid & 1) * 16;     // 0 or 16

    float4 a_pf[4];
    float  b_pf[16];

    auto ldg_chunk = [&](int k0) {
        #pragma unroll
        for (int i = 0; i < 4; ++i) {
            int lin = tid + 256*i;
            int r = lin >> 3, j = lin & 7;
            a_pf[i] = *reinterpret_cast<const float4*>(
                A + (size_t)(m0 + r) * K + k0 + j * 4);
        }
        #pragma unroll
        for (int i = 0; i < 16; ++i)
            b_pf[i] = W[(size_t)(k0 + kb + i) * N + n0 + nloc];
    };
    auto sts_chunk = [&](uint32_t* sA, uint32_t* sB) {
        #pragma unroll
        for (int i = 0; i < 4; ++i) {
            int lin = tid + 256*i;
            int r = lin >> 3, j = lin & 7;
            uint4 t;
            t.x = cvt_tf32(a_pf[i].x);
            t.y = cvt_tf32(a_pf[i].y);
            t.z = cvt_tf32(a_pf[i].z);
            t.w = cvt_tf32(a_pf[i].w);
            *reinterpret_cast<uint4*>(&sA[r * SSTR + j * 4]) = t;
        }
        #pragma unroll
        for (int i = 0; i < 16; ++i)
            sB[nloc * SSTR + kb + i] = cvt_tf32(b_pf[i]);
    };

    float acc[16][4];
    #pragma unroll
    for (int t = 0; t < 16; ++t)
        #pragma unroll
        for (int e = 0; e < 4; ++e) acc[t][e] = 0.f;

    const int qrow = lane >> 2;
    const int qcol = lane & 3;

    // prologue: chunk0 -> stage0; prefetch chunk1
    ldg_chunk(0);
    sts_chunk(stA[0], stB[0]);
    ldg_chunk(BK);
    __syncthreads();

    for (int c = 0; c < NCHUNK; ++c) {
        const uint32_t* sA = stA[c & 1];
        const uint32_t* sB = stB[c & 1];

        // STS chunk c+1 into the other stage (regs hold c+1 data)
        if (c + 1 < NCHUNK) sts_chunk(stA[(c + 1) & 1], stB[(c + 1) & 1]);
        // refill regs with chunk c+2
        if (c + 2 < NCHUNK) ldg_chunk((c + 2) * BK);

        // MMA phase on chunk c
        #pragma unroll
        for (int ks = 0; ks < 4; ++ks) {
            const int kbase = ks * 8 + qcol;
            uint32_t af[4][4];
            #pragma unroll
            for (int i = 0; i < 4; ++i) {
                const uint32_t* p = &sA[(wm + i*16 + qrow) * SSTR + kbase];
                af[i][0] = p[0];
                af[i][1] = p[8 * SSTR];
                af[i][2] = p[4];
                af[i][3] = p[8 * SSTR + 4];
            }
            uint32_t bf[4][2];
            #pragma unroll
            for (int j = 0; j < 4; ++j) {
                const uint32_t* p = &sB[(wn + j*8 + qrow) * SSTR + kbase];
                bf[j][0] = p[0];
                bf[j][1] = p[4];
            }
            #pragma unroll
            for (int i = 0; i < 4; ++i)
                #pragma unroll
                for (int j = 0; j < 4; ++j)
                    mma_tf32(acc[i*4 + j],
                             af[i][0], af[i][1], af[i][2], af[i][3],
                             bf[j][0], bf[j][1]);
        }

        __syncthreads();
    }

    // ---- epilogue: bias + (optional) head-split scatter ----
    #pragma unroll
    for (int i = 0; i < 4; ++i) {
        #pragma unroll
        for (int j = 0; j < 4; ++j) {
            const float* a4 = acc[i*4 + j];
            const int colg  = n0 + wn + j*8 + 2*qcol;
            const float2 bv = *reinterpret_cast<const float2*>(bias + colg);
            #pragma unroll
            for (int half = 0; half < 2; ++half) {
                const int m = m0 + wm + i*16 + qrow + half*8;
                float2 o;
                o.x = a4[half*2 + 0] + bv.x;
                o.y = a4[half*2 + 1] + bv.y;
                size_t idx;
                if (SCATTER) {
                    const int b = m >> 11;
                    const int s = m & (NS - 1);
                    const int h = colg >> 6;
                    const int hd = colg & 63;
                    idx = (((size_t)(b*NH + h))*NS + s)*NHD + hd;
                } else {
                    idx = (size_t)m * N + colg;
                }
                *reinterpret_cast<float2*>(C + idx) = o;
            }
        }
    }
}

// ---------------------------------------------------------------------------
// Tensor-core flash attention (tf32 mma.sync), causal. UNCHANGED from R7.
// ---------------------------------------------------------------------------
#define AQ_STR   68
#define AP_STR   36
#define OFF_Q    0              // 128*68 = 8704
#define OFF_K    8704           // 64*68  = 4352
#define OFF_VT   13056          // 64*68  = 4352
#define OFF_P    17408          // 8*16*36 = 4608
#define SMEM_WORDS 22016        // *4 = 88064 B

__global__ void __launch_bounds__(256, 2)
attn_tc(const float* __restrict__ Q, const float* __restrict__ K,
        const float* __restrict__ V, float* __restrict__ O)
{
    extern __shared__ uint32_t sm[];
    uint32_t* sQ  = sm + OFF_Q;
    uint32_t* sK  = sm + OFF_K;
    uint32_t* sVt = sm + OFF_VT;

    const int tid  = threadIdx.x;
    const int wid  = tid >> 5;
    const int lane = tid & 31;
    const int qrow = lane >> 2;   // 0..7
    const int qcol = lane & 3;    // 0..3
    const int wm   = wid * 16;

    const int qt = (NS/128 - 1) - blockIdx.x;
    const int h  = blockIdx.y;
    const int b  = blockIdx.z;
    const int bh = b*NH + h;

    const float* Qb = Q + (size_t)bh * NS * NHD;
    const float* Kb = K + (size_t)bh * NS * NHD;
    const float* Vb = V + (size_t)bh * NS * NHD;

    const int kr = tid >> 4;
    const int kc = (tid & 15) * 4;
    const int vkey = tid & 63;
    const int vdg  = (tid >> 6) * 16;

    #pragma unroll
    for (int p = 0; p < 8; ++p) {
        int lin = tid + 256*p;
        int r = lin >> 4, c = (lin & 15) * 4;
        float4 qv = *reinterpret_cast<const float4*>(
            Qb + (size_t)(qt*128 + r)*NHD + c);
        uint32_t* d = &sQ[r * AQ_STR + c];
        d[0] = cvt_tf32(qv.x);
        d[1] = cvt_tf32(qv.y);
        d[2] = cvt_tf32(qv.z);
        d[3] = cvt_tf32(qv.w);
    }

    float o[8][4];
    #pragma unroll
    for (int nt = 0; nt < 8; ++nt)
        #pragma unroll
        for (int e = 0; e < 4; ++e) o[nt][e] = 0.f;
    float mrow[2] = {-1e30f, -1e30f};
    float lrow[2] = {0.f, 0.f};

    const int jmax = 2*qt + 1;

    float4 kreg[4], vreg[4];
    #pragma unroll
    for (int p = 0; p < 4; ++p)
        kreg[p] = *reinterpret_cast<const float4*>(
            Kb + (size_t)(kr + p*16)*NHD + kc);
    #pragma unroll
    for (int g = 0; g < 4; ++g)
        vreg[g] = *reinterpret_cast<const float4*>(
            Vb + (size_t)vkey*NHD + vdg + g*4);

    for (int j = 0; j <= jmax; ++j) {
        __syncthreads();

        #pragma unroll
        for (int p = 0; p < 4; ++p) {
            uint4 t;
            t.x = cvt_tf32(kreg[p].x);
            t.y = cvt_tf32(kreg[p].y);
            t.z = cvt_tf32(kreg[p].z);
            t.w = cvt_tf32(kreg[p].w);
            *reinterpret_cast<uint4*>(&sK[(kr + p*16) * AQ_STR + kc]) = t;
        }
        #pragma unroll
        for (int g = 0; g < 4; ++g) {
            float f[4] = {vreg[g].x, vreg[g].y, vreg[g].z, vreg[g].w};
            #pragma unroll
            for (int e = 0; e < 4; ++e)
                sVt[(vdg + g*4 + e) * AQ_STR + vkey] = cvt_tf32(f[e]);
        }

        if (j < jmax) {
            const size_t rb = (size_t)(j + 1) * 64;
            #pragma unroll
            for (int p = 0; p < 4; ++p)
                kreg[p] = *reinterpret_cast<const float4*>(
                    Kb + (rb + kr + p*16)*NHD + kc);
            #pragma unroll
            for (int g = 0; g < 4; ++g)
                vreg[g] = *reinterpret_cast<const float4*>(
                    Vb + (rb + vkey)*NHD + vdg + g*4);
        }

        __syncthreads();

        const bool active = (j*64 <= qt*128 + wm + 15);
        if (active) {
            float s[8][4];
            #pragma unroll
            for (int nt = 0; nt < 8; ++nt)
                #pragma unroll
                for (int e = 0; e < 4; ++e) s[nt][e] = 0.f;

            #pragma unroll
            for (int ks = 0; ks < 8; ++ks) {
                const uint32_t* qp = &sQ[(wm + qrow) * AQ_STR + ks*8 + qcol];
                uint32_t a0 = qp[0], a1 = qp[8*AQ_STR], a2 = qp[4], a3 = qp[8*AQ_STR + 4];
                #pragma unroll
                for (int nt = 0; nt < 8; ++nt) {
                    const int off = (nt*8 + qrow) * AQ_STR + ks*8 + qcol;
                    mma_tf32(s[nt], a0, a1, a2, a3, sK[off], sK[off + 4]);
                }
            }

            const bool need_mask = (j >= 2*qt);
            #pragma unroll
            for (int r = 0; r < 2; ++r) {
                const int rowg = qt*128 + wm + qrow + r*8;
                float mx = -1e30f;
                #pragma unroll
                for (int nt = 0; nt < 8; ++nt) {
                    const int colg = j*64 + nt*8 + 2*qcol;
                    float v0 = s[nt][r*2 + 0] * SCALE_F;
                    float v1 = s[nt][r*2 + 1] * SCALE_F;
                    if (need_mask) {
                        if (colg     > rowg) v0 = -1e30f;
                        if (colg + 1 > rowg) v1 = -1e30f;
                    }
                    s[nt][r*2 + 0] = v0;
                    s[nt][r*2 + 1] = v1;
                    mx = fmaxf(mx, fmaxf(v0, v1));
                }
                mx = fmaxf(mx, __shfl_xor_sync(0xffffffffu, mx, 1));
                mx = fmaxf(mx, __shfl_xor_sync(0xffffffffu, mx, 2));
                const float mn    = fmaxf(mrow[r], mx);
                const float alpha = __expf(mrow[r] - mn);
                mrow[r] = mn;
                float ls = 0.f;
                #pragma unroll
                for (int nt = 0; nt < 8; ++nt) {
                    float p0 = __expf(s[nt][r*2 + 0] - mn);
                    float p1 = __expf(s[nt][r*2 + 1] - mn);
                    s[nt][r*2 + 0] = p0;
                    s[nt][r*2 + 1] = p1;
                    ls += p0 + p1;
                }
                ls += __shfl_xor_sync(0xffffffffu, ls, 1);
                ls += __shfl_xor_sync(0xffffffffu, ls, 2);
                lrow[r] = lrow[r]*alpha + ls;
                #pragma unroll
                for (int nt = 0; nt < 8; ++nt) {
                    o[nt][r*2 + 0] *= alpha;
                    o[nt][r*2 + 1] *= alpha;
                }
            }

            uint32_t* sPw = sm + OFF_P + wid * (16 * AP_STR);
            #pragma unroll
            for (int kh = 0; kh < 2; ++kh) {
                __syncwarp();
                #pragma unroll
                for (int t = 0; t < 4; ++t) {
                    const int nt = kh*4 + t;
                    const int lc = t*8 + 2*qcol;
                    sPw[qrow * AP_STR + lc]           = cvt_tf32(s[nt][0]);
                    sPw[qrow * AP_STR + lc + 1]       = cvt_tf32(s[nt][1]);
                    sPw[(qrow + 8) * AP_STR + lc]     = cvt_tf32(s[nt][2]);
                    sPw[(qrow + 8) * AP_STR + lc + 1] = cvt_tf32(s[nt][3]);
                }
                __syncwarp();
                #pragma unroll
                for (int ks = 0; ks < 4; ++ks) {
                    const uint32_t* p0 = &sPw[qrow * AP_STR + ks*8 + qcol];
                    const uint32_t* p1 = &sPw[(qrow + 8) * AP_STR + ks*8 + qcol];
                    uint32_t a0 = p0[0], a1 = p1[0], a2 = p0[4], a3 = p1[4];
                    #pragma unroll
                    for (int nt = 0; nt < 8; ++nt) {
                        const int off = (nt*8 + qrow) * AQ_STR + kh*32 + ks*8 + qcol;
                        mma_tf32(o[nt], a0, a1, a2, a3, sVt[off], sVt[off + 4]);
                    }
                }
            }
        }
    }

    #pragma unroll
    for (int r = 0; r < 2; ++r) {
        const float inv = 1.0f / lrow[r];
        const int rowg = qt*128 + wm + qrow + r*8;
        #pragma unroll
        for (int nt = 0; nt < 8; ++nt) {
            const int col = h*NHD + nt*8 + 2*qcol;
            float2 ov;
            ov.x = o[nt][r*2 + 0] * inv;
            ov.y = o[nt][r*2 + 1] * inv;
            *reinterpret_cast<float2*>(
                O + ((size_t)b*NS + rowg)*ND + col) = ov;
        }
    }
}

// ---------------------------------------------------------------------------
extern "C" void kernel_launch(void* const* d_in, const int* in_sizes, int n_in,
                              void* d_out, int out_size)
{
    const float* x  = (const float*)d_in[0];
    const float* wq = (const float*)d_in[1];
    const float* bq = (const float*)d_in[2];
    const float* wk = (const float*)d_in[3];
    const float* bk = (const float*)d_in[4];
    const float* wv = (const float*)d_in[5];
    const float* bv = (const float*)d_in[6];
    const float* wo = (const float*)d_in[7];
    const float* bo = (const float*)d_in[8];
    float* out = (float*)d_out;

    float *q, *k, *v, *att;
    cudaGetSymbolAddress((void**)&q,   g_q);
    cudaGetSymbolAddress((void**)&k,   g_k);
    cudaGetSymbolAddress((void**)&v,   g_v);
    cudaGetSymbolAddress((void**)&att, g_att);

    static bool attr_done = false;
    if (!attr_done) {
        cudaFuncSetAttribute(attn_tc,
            cudaFuncAttributeMaxDynamicSharedMemorySize, SMEM_WORDS * 4);
        cudaFuncSetAttribute(gemm_db<true>,
            cudaFuncAttributeMaxDynamicSharedMemorySize, GEMM_SMEM_BYTES);
        cudaFuncSetAttribute(gemm_db<false>,
            cudaFuncAttributeMaxDynamicSharedMemorySize, GEMM_SMEM_BYTES);
        attr_done = true;
    }

    // Fused QKV projection: one launch, grid.z selects W/bias/output
    dim3 qkv_grid(ND/128, NM/128, 3);   // (8, 32, 3) = 768 CTAs
    gemm_db<true><<<qkv_grid, 256, GEMM_SMEM_BYTES>>>(
        x, wq, bq, q, wk, bk, k, wv, bv, v);

    dim3 agrid(NS/128, NH, NB);         // (16, 16, 2)
    attn_tc<<<agrid, 256, SMEM_WORDS * 4>>>(q, k, v, att);

    // Output projection
    dim3 ogrid(ND/128, NM/128, 1);
    gemm_db<false><<<ogrid, 256, GEMM_SMEM_BYTES>>>(
        att, wo, bo, out, wo, bo, out, wo, bo, out);
}

// round 10
// speedup vs baseline: 1.1077x; 1.1077x over previous
#include <cuda_runtime.h>
#include <cstdint>

// Problem constants
#define NB 2
#define NS 2048
#define ND 1024
#define NH 16
#define NHD 64
#define NM (NB*NS)
#define SCALE_F 0.125f      // 64^-0.5

// Scratch (alloc-free rule: __device__ globals)
__device__ float g_q[NB*NH*NS*NHD];
__device__ float g_k[NB*NH*NS*NHD];
__device__ float g_v[NB*NH*NS*NHD];
__device__ float g_att[NB*NS*ND];

// ---------------------------------------------------------------------------
__device__ __forceinline__ uint32_t cvt_tf32(float f) {
    uint32_t r;
    asm("cvt.rna.tf32.f32 %0, %1;" : "=r"(r) : "f"(f));
    return r;
}

__device__ __forceinline__ void mma_tf32(float c[4],
                                         uint32_t a0, uint32_t a1,
                                         uint32_t a2, uint32_t a3,
                                         uint32_t b0, uint32_t b1) {
    asm volatile(
        "mma.sync.aligned.m16n8k8.row.col.f32.tf32.tf32.f32 "
        "{%0,%1,%2,%3}, {%4,%5,%6,%7}, {%8,%9}, {%0,%1,%2,%3};"
        : "+f"(c[0]), "+f"(c[1]), "+f"(c[2]), "+f"(c[3])
        : "r"(a0), "r"(a1), "r"(a2), "r"(a3), "r"(b0), "r"(b1));
}

// ---------------------------------------------------------------------------
// tf32 mma.sync GEMM — R7's proven single-buffered body, now with grid.z
// selecting one of up to three (W, bias, C) triples (fused QKV launch).
// CTA 128x128, BK=32, 8 warps (2 M x 4 N).
// SCATTER=true writes [B,H,S,HD] (fused head-split transpose).
// ---------------------------------------------------------------------------
#define SSTR 36

template<bool SCATTER>
__global__ void __launch_bounds__(256)
gemm_tc(const float* __restrict__ A,
        const float* __restrict__ W0, const float* __restrict__ b0, float* __restrict__ C0,
        const float* __restrict__ W1, const float* __restrict__ b1, float* __restrict__ C1,
        const float* __restrict__ W2, const float* __restrict__ b2, float* __restrict__ C2)
{
    constexpr int N = ND, K = ND;
    constexpr int BK = 32;
    constexpr int NCHUNK = K / BK;

    __shared__ uint32_t sA[128 * SSTR];
    __shared__ uint32_t sB[128 * SSTR];

    const float* W;
    const float* bias;
    float* C;
    if (blockIdx.z == 0)      { W = W0; bias = b0; C = C0; }
    else if (blockIdx.z == 1) { W = W1; bias = b1; C = C1; }
    else                      { W = W2; bias = b2; C = C2; }

    const int tid  = threadIdx.x;
    const int wid  = tid >> 5;
    const int lane = tid & 31;
    const int m0   = blockIdx.y * 128;
    const int n0   = blockIdx.x * 128;

    const int wm = (wid >> 2) * 64;
    const int wn = (wid & 3)  * 32;

    const int nloc = tid & 127;
    const int kb   = (tid >> 7) * 16;

    float4 a_pf[4];
    float  b_pf[16];
    {
        #pragma unroll
        for (int i = 0; i < 4; ++i) {
            int lin = tid + 256*i;
            int r = lin >> 3, j = lin & 7;
            a_pf[i] = *reinterpret_cast<const float4*>(
                A + (size_t)(m0 + r) * K + j * 4);
        }
        #pragma unroll
        for (int i = 0; i < 16; ++i)
            b_pf[i] = W[(size_t)(kb + i) * N + n0 + nloc];
    }

    float acc[16][4];
    #pragma unroll
    for (int t = 0; t < 16; ++t)
        #pragma unroll
        for (int e = 0; e < 4; ++e) acc[t][e] = 0.f;

    const int qrow = lane >> 2;
    const int qcol = lane & 3;

    for (int c = 0; c < NCHUNK; ++c) {
        if (c > 0) __syncthreads();

        #pragma unroll
        for (int i = 0; i < 4; ++i) {
            int lin = tid + 256*i;
            int r = lin >> 3, j = lin & 7;
            uint4 t;
            t.x = cvt_tf32(a_pf[i].x);
            t.y = cvt_tf32(a_pf[i].y);
            t.z = cvt_tf32(a_pf[i].z);
            t.w = cvt_tf32(a_pf[i].w);
            *reinterpret_cast<uint4*>(&sA[r * SSTR + j * 4]) = t;
        }
        #pragma unroll
        for (int i = 0; i < 16; ++i)
            sB[nloc * SSTR + kb + i] = cvt_tf32(b_pf[i]);

        if (c + 1 < NCHUNK) {
            const int k0n = (c + 1) * BK;
            #pragma unroll
            for (int i = 0; i < 4; ++i) {
                int lin = tid + 256*i;
                int r = lin >> 3, j = lin & 7;
                a_pf[i] = *reinterpret_cast<const float4*>(
                    A + (size_t)(m0 + r) * K + k0n + j * 4);
            }
            #pragma unroll
            for (int i = 0; i < 16; ++i)
                b_pf[i] = W[(size_t)(k0n + kb + i) * N + n0 + nloc];
        }

        __syncthreads();

        #pragma unroll
        for (int ks = 0; ks < 4; ++ks) {
            const int kbase = ks * 8 + qcol;
            uint32_t af[4][4];
            #pragma unroll
            for (int i = 0; i < 4; ++i) {
                const uint32_t* p = &sA[(wm + i*16 + qrow) * SSTR + kbase];
                af[i][0] = p[0];
                af[i][1] = p[8 * SSTR];
                af[i][2] = p[4];
                af[i][3] = p[8 * SSTR + 4];
            }
            uint32_t bf[4][2];
            #pragma unroll
            for (int j = 0; j < 4; ++j) {
                const uint32_t* p = &sB[(wn + j*8 + qrow) * SSTR + kbase];
                bf[j][0] = p[0];
                bf[j][1] = p[4];
            }
            #pragma unroll
            for (int i = 0; i < 4; ++i)
                #pragma unroll
                for (int j = 0; j < 4; ++j)
                    mma_tf32(acc[i*4 + j],
                             af[i][0], af[i][1], af[i][2], af[i][3],
                             bf[j][0], bf[j][1]);
        }
    }

    #pragma unroll
    for (int i = 0; i < 4; ++i) {
        #pragma unroll
        for (int j = 0; j < 4; ++j) {
            const float* a4 = acc[i*4 + j];
            const int colg  = n0 + wn + j*8 + 2*qcol;
            const float2 bv = *reinterpret_cast<const float2*>(bias + colg);
            #pragma unroll
            for (int half = 0; half < 2; ++half) {
                const int m = m0 + wm + i*16 + qrow + half*8;
                float2 o;
                o.x = a4[half*2 + 0] + bv.x;
                o.y = a4[half*2 + 1] + bv.y;
                size_t idx;
                if (SCATTER) {
                    const int b = m >> 11;
                    const int s = m & (NS - 1);
                    const int h = colg >> 6;
                    const int hd = colg & 63;
                    idx = (((size_t)(b*NH + h))*NS + s)*NHD + hd;
                } else {
                    idx = (size_t)m * N + colg;
                }
                *reinterpret_cast<float2*>(C + idx) = o;
            }
        }
    }
}

// ---------------------------------------------------------------------------
// Tensor-core flash attention (tf32 mma.sync), causal. UNCHANGED from R7.
// ---------------------------------------------------------------------------
#define AQ_STR   68
#define AP_STR   36
#define OFF_Q    0              // 128*68 = 8704
#define OFF_K    8704           // 64*68  = 4352
#define OFF_VT   13056          // 64*68  = 4352
#define OFF_P    17408          // 8*16*36 = 4608
#define SMEM_WORDS 22016        // *4 = 88064 B

__global__ void __launch_bounds__(256, 2)
attn_tc(const float* __restrict__ Q, const float* __restrict__ K,
        const float* __restrict__ V, float* __restrict__ O)
{
    extern __shared__ uint32_t sm[];
    uint32_t* sQ  = sm + OFF_Q;
    uint32_t* sK  = sm + OFF_K;
    uint32_t* sVt = sm + OFF_VT;

    const int tid  = threadIdx.x;
    const int wid  = tid >> 5;
    const int lane = tid & 31;
    const int qrow = lane >> 2;   // 0..7
    const int qcol = lane & 3;    // 0..3
    const int wm   = wid * 16;

    const int qt = (NS/128 - 1) - blockIdx.x;
    const int h  = blockIdx.y;
    const int b  = blockIdx.z;
    const int bh = b*NH + h;

    const float* Qb = Q + (size_t)bh * NS * NHD;
    const float* Kb = K + (size_t)bh * NS * NHD;
    const float* Vb = V + (size_t)bh * NS * NHD;

    const int kr = tid >> 4;
    const int kc = (tid & 15) * 4;
    const int vkey = tid & 63;
    const int vdg  = (tid >> 6) * 16;

    #pragma unroll
    for (int p = 0; p < 8; ++p) {
        int lin = tid + 256*p;
        int r = lin >> 4, c = (lin & 15) * 4;
        float4 qv = *reinterpret_cast<const float4*>(
            Qb + (size_t)(qt*128 + r)*NHD + c);
        uint32_t* d = &sQ[r * AQ_STR + c];
        d[0] = cvt_tf32(qv.x);
        d[1] = cvt_tf32(qv.y);
        d[2] = cvt_tf32(qv.z);
        d[3] = cvt_tf32(qv.w);
    }

    float o[8][4];
    #pragma unroll
    for (int nt = 0; nt < 8; ++nt)
        #pragma unroll
        for (int e = 0; e < 4; ++e) o[nt][e] = 0.f;
    float mrow[2] = {-1e30f, -1e30f};
    float lrow[2] = {0.f, 0.f};

    const int jmax = 2*qt + 1;

    float4 kreg[4], vreg[4];
    #pragma unroll
    for (int p = 0; p < 4; ++p)
        kreg[p] = *reinterpret_cast<const float4*>(
            Kb + (size_t)(kr + p*16)*NHD + kc);
    #pragma unroll
    for (int g = 0; g < 4; ++g)
        vreg[g] = *reinterpret_cast<const float4*>(
            Vb + (size_t)vkey*NHD + vdg + g*4);

    for (int j = 0; j <= jmax; ++j) {
        __syncthreads();

        #pragma unroll
        for (int p = 0; p < 4; ++p) {
            uint4 t;
            t.x = cvt_tf32(kreg[p].x);
            t.y = cvt_tf32(kreg[p].y);
            t.z = cvt_tf32(kreg[p].z);
            t.w = cvt_tf32(kreg[p].w);
            *reinterpret_cast<uint4*>(&sK[(kr + p*16) * AQ_STR + kc]) = t;
        }
        #pragma unroll
        for (int g = 0; g < 4; ++g) {
            float f[4] = {vreg[g].x, vreg[g].y, vreg[g].z, vreg[g].w};
            #pragma unroll
            for (int e = 0; e < 4; ++e)
                sVt[(vdg + g*4 + e) * AQ_STR + vkey] = cvt_tf32(f[e]);
        }

        if (j < jmax) {
            const size_t rb = (size_t)(j + 1) * 64;
            #pragma unroll
            for (int p = 0; p < 4; ++p)
                kreg[p] = *reinterpret_cast<const float4*>(
                    Kb + (rb + kr + p*16)*NHD + kc);
            #pragma unroll
            for (int g = 0; g < 4; ++g)
                vreg[g] = *reinterpret_cast<const float4*>(
                    Vb + (rb + vkey)*NHD + vdg + g*4);
        }

        __syncthreads();

        const bool active = (j*64 <= qt*128 + wm + 15);
        if (active) {
            float s[8][4];
            #pragma unroll
            for (int nt = 0; nt < 8; ++nt)
                #pragma unroll
                for (int e = 0; e < 4; ++e) s[nt][e] = 0.f;

            #pragma unroll
            for (int ks = 0; ks < 8; ++ks) {
                const uint32_t* qp = &sQ[(wm + qrow) * AQ_STR + ks*8 + qcol];
                uint32_t a0 = qp[0], a1 = qp[8*AQ_STR], a2 = qp[4], a3 = qp[8*AQ_STR + 4];
                #pragma unroll
                for (int nt = 0; nt < 8; ++nt) {
                    const int off = (nt*8 + qrow) * AQ_STR + ks*8 + qcol;
                    mma_tf32(s[nt], a0, a1, a2, a3, sK[off], sK[off + 4]);
                }
            }

            const bool need_mask = (j >= 2*qt);
            #pragma unroll
            for (int r = 0; r < 2; ++r) {
                const int rowg = qt*128 + wm + qrow + r*8;
                float mx = -1e30f;
                #pragma unroll
                for (int nt = 0; nt < 8; ++nt) {
                    const int colg = j*64 + nt*8 + 2*qcol;
                    float v0 = s[nt][r*2 + 0] * SCALE_F;
                    float v1 = s[nt][r*2 + 1] * SCALE_F;
                    if (need_mask) {
                        if (colg     > rowg) v0 = -1e30f;
                        if (colg + 1 > rowg) v1 = -1e30f;
                    }
                    s[nt][r*2 + 0] = v0;
                    s[nt][r*2 + 1] = v1;
                    mx = fmaxf(mx, fmaxf(v0, v1));
                }
                mx = fmaxf(mx, __shfl_xor_sync(0xffffffffu, mx, 1));
                mx = fmaxf(mx, __shfl_xor_sync(0xffffffffu, mx, 2));
                const float mn    = fmaxf(mrow[r], mx);
                const float alpha = __expf(mrow[r] - mn);
                mrow[r] = mn;
                float ls = 0.f;
                #pragma unroll
                for (int nt = 0; nt < 8; ++nt) {
                    float p0 = __expf(s[nt][r*2 + 0] - mn);
                    float p1 = __expf(s[nt][r*2 + 1] - mn);
                    s[nt][r*2 + 0] = p0;
                    s[nt][r*2 + 1] = p1;
                    ls += p0 + p1;
                }
                ls += __shfl_xor_sync(0xffffffffu, ls, 1);
                ls += __shfl_xor_sync(0xffffffffu, ls, 2);
                lrow[r] = lrow[r]*alpha + ls;
                #pragma unroll
                for (int nt = 0; nt < 8; ++nt) {
                    o[nt][r*2 + 0] *= alpha;
                    o[nt][r*2 + 1] *= alpha;
                }
            }

            uint32_t* sPw = sm + OFF_P + wid * (16 * AP_STR);
            #pragma unroll
            for (int kh = 0; kh < 2; ++kh) {
                __syncwarp();
                #pragma unroll
                for (int t = 0; t < 4; ++t) {
                    const int nt = kh*4 + t;
                    const int lc = t*8 + 2*qcol;
                    sPw[qrow * AP_STR + lc]           = cvt_tf32(s[nt][0]);
                    sPw[qrow * AP_STR + lc + 1]       = cvt_tf32(s[nt][1]);
                    sPw[(qrow + 8) * AP_STR + lc]     = cvt_tf32(s[nt][2]);
                    sPw[(qrow + 8) * AP_STR + lc + 1] = cvt_tf32(s[nt][3]);
                }
                __syncwarp();
                #pragma unroll
                for (int ks = 0; ks < 4; ++ks) {
                    const uint32_t* p0 = &sPw[qrow * AP_STR + ks*8 + qcol];
                    const uint32_t* p1 = &sPw[(qrow + 8) * AP_STR + ks*8 + qcol];
                    uint32_t a0 = p0[0], a1 = p1[0], a2 = p0[4], a3 = p1[4];
                    #pragma unroll
                    for (int nt = 0; nt < 8; ++nt) {
                        const int off = (nt*8 + qrow) * AQ_STR + kh*32 + ks*8 + qcol;
                        mma_tf32(o[nt], a0, a1, a2, a3, sVt[off], sVt[off + 4]);
                    }
                }
            }
        }
    }

    #pragma unroll
    for (int r = 0; r < 2; ++r) {
        const float inv = 1.0f / lrow[r];
        const int rowg = qt*128 + wm + qrow + r*8;
        #pragma unroll
        for (int nt = 0; nt < 8; ++nt) {
            const int col = h*NHD + nt*8 + 2*qcol;
            float2 ov;
            ov.x = o[nt][r*2 + 0] * inv;
            ov.y = o[nt][r*2 + 1] * inv;
            *reinterpret_cast<float2*>(
                O + ((size_t)b*NS + rowg)*ND + col) = ov;
        }
    }
}

// ---------------------------------------------------------------------------
extern "C" void kernel_launch(void* const* d_in, const int* in_sizes, int n_in,
                              void* d_out, int out_size)
{
    const float* x  = (const float*)d_in[0];
    const float* wq = (const float*)d_in[1];
    const float* bq = (const float*)d_in[2];
    const float* wk = (const float*)d_in[3];
    const float* bk = (const float*)d_in[4];
    const float* wv = (const float*)d_in[5];
    const float* bv = (const float*)d_in[6];
    const float* wo = (const float*)d_in[7];
    const float* bo = (const float*)d_in[8];
    float* out = (float*)d_out;

    float *q, *k, *v, *att;
    cudaGetSymbolAddress((void**)&q,   g_q);
    cudaGetSymbolAddress((void**)&k,   g_k);
    cudaGetSymbolAddress((void**)&v,   g_v);
    cudaGetSymbolAddress((void**)&att, g_att);

    static bool attr_done = false;
    if (!attr_done) {
        cudaFuncSetAttribute(attn_tc,
            cudaFuncAttributeMaxDynamicSharedMemorySize, SMEM_WORDS * 4);
        attr_done = true;
    }

    // Fused QKV projection: one launch, grid.z selects W/bias/output,
    // single-buffered R7 GEMM body (measured-fast).
    dim3 qkv_grid(ND/128, NM/128, 3);   // (8, 32, 3) = 768 CTAs
    gemm_tc<true><<<qkv_grid, 256>>>(
        x, wq, bq, q, wk, bk, k, wv, bv, v);

    dim3 agrid(NS/128, NH, NB);         // (16, 16, 2)
    attn_tc<<<agrid, 256, SMEM_WORDS * 4>>>(q, k, v, att);

    // Output projection (z=1)
    dim3 ogrid(ND/128, NM/128, 1);
    gemm_tc<false><<<ogrid, 256>>>(
        att, wo, bo, out, wo, bo, out, wo, bo, out);
}

// round 11
// speedup vs baseline: 1.1095x; 1.0017x over previous
#include <cuda_runtime.h>
#include <cstdint>

// Problem constants
#define NB 2
#define NS 2048
#define ND 1024
#define NH 16
#define NHD 64
#define NM (NB*NS)
#define SCALE_F 0.125f      // 64^-0.5

// Scratch (alloc-free rule: __device__ globals)
__device__ float g_q[NB*NH*NS*NHD];
__device__ float g_k[NB*NH*NS*NHD];
__device__ float g_v[NB*NH*NS*NHD];
__device__ float g_att[NB*NS*ND];

// ---------------------------------------------------------------------------
__device__ __forceinline__ uint32_t cvt_tf32(float f) {
    uint32_t r;
    asm("cvt.rna.tf32.f32 %0, %1;" : "=r"(r) : "f"(f));
    return r;
}

__device__ __forceinline__ void mma_tf32(float c[4],
                                         uint32_t a0, uint32_t a1,
                                         uint32_t a2, uint32_t a3,
                                         uint32_t b0, uint32_t b1) {
    asm volatile(
        "mma.sync.aligned.m16n8k8.row.col.f32.tf32.tf32.f32 "
        "{%0,%1,%2,%3}, {%4,%5,%6,%7}, {%8,%9}, {%0,%1,%2,%3};"
        : "+f"(c[0]), "+f"(c[1]), "+f"(c[2]), "+f"(c[3])
        : "r"(a0), "r"(a1), "r"(a2), "r"(a3), "r"(b0), "r"(b1));
}

// ---------------------------------------------------------------------------
// tf32 mma.sync GEMM — UNCHANGED from R9 (passing). grid.z selects
// (W, bias, C) triple. CTA 128x128, BK=32, 8 warps.
// ---------------------------------------------------------------------------
#define SSTR 36

template<bool SCATTER>
__global__ void __launch_bounds__(256)
gemm_tc(const float* __restrict__ A,
        const float* __restrict__ W0, const float* __restrict__ b0, float* __restrict__ C0,
        const float* __restrict__ W1, const float* __restrict__ b1, float* __restrict__ C1,
        const float* __restrict__ W2, const float* __restrict__ b2, float* __restrict__ C2)
{
    constexpr int N = ND, K = ND;
    constexpr int BK = 32;
    constexpr int NCHUNK = K / BK;

    __shared__ uint32_t sA[128 * SSTR];
    __shared__ uint32_t sB[128 * SSTR];

    const float* W;
    const float* bias;
    float* C;
    if (blockIdx.z == 0)      { W = W0; bias = b0; C = C0; }
    else if (blockIdx.z == 1) { W = W1; bias = b1; C = C1; }
    else                      { W = W2; bias = b2; C = C2; }

    const int tid  = threadIdx.x;
    const int wid  = tid >> 5;
    const int lane = tid & 31;
    const int m0   = blockIdx.y * 128;
    const int n0   = blockIdx.x * 128;

    const int wm = (wid >> 2) * 64;
    const int wn = (wid & 3)  * 32;

    const int nloc = tid & 127;
    const int kb   = (tid >> 7) * 16;

    float4 a_pf[4];
    float  b_pf[16];
    {
        #pragma unroll
        for (int i = 0; i < 4; ++i) {
            int lin = tid + 256*i;
            int r = lin >> 3, j = lin & 7;
            a_pf[i] = *reinterpret_cast<const float4*>(
                A + (size_t)(m0 + r) * K + j * 4);
        }
        #pragma unroll
        for (int i = 0; i < 16; ++i)
            b_pf[i] = W[(size_t)(kb + i) * N + n0 + nloc];
    }

    float acc[16][4];
    #pragma unroll
    for (int t = 0; t < 16; ++t)
        #pragma unroll
        for (int e = 0; e < 4; ++e) acc[t][e] = 0.f;

    const int qrow = lane >> 2;
    const int qcol = lane & 3;

    for (int c = 0; c < NCHUNK; ++c) {
        if (c > 0) __syncthreads();

        #pragma unroll
        for (int i = 0; i < 4; ++i) {
            int lin = tid + 256*i;
            int r = lin >> 3, j = lin & 7;
            uint4 t;
            t.x = cvt_tf32(a_pf[i].x);
            t.y = cvt_tf32(a_pf[i].y);
            t.z = cvt_tf32(a_pf[i].z);
            t.w = cvt_tf32(a_pf[i].w);
            *reinterpret_cast<uint4*>(&sA[r * SSTR + j * 4]) = t;
        }
        #pragma unroll
        for (int i = 0; i < 16; ++i)
            sB[nloc * SSTR + kb + i] = cvt_tf32(b_pf[i]);

        if (c + 1 < NCHUNK) {
            const int k0n = (c + 1) * BK;
            #pragma unroll
            for (int i = 0; i < 4; ++i) {
                int lin = tid + 256*i;
                int r = lin >> 3, j = lin & 7;
                a_pf[i] = *reinterpret_cast<const float4*>(
                    A + (size_t)(m0 + r) * K + k0n + j * 4);
            }
            #pragma unroll
            for (int i = 0; i < 16; ++i)
                b_pf[i] = W[(size_t)(k0n + kb + i) * N + n0 + nloc];
        }

        __syncthreads();

        #pragma unroll
        for (int ks = 0; ks < 4; ++ks) {
            const int kbase = ks * 8 + qcol;
            uint32_t af[4][4];
            #pragma unroll
            for (int i = 0; i < 4; ++i) {
                const uint32_t* p = &sA[(wm + i*16 + qrow) * SSTR + kbase];
                af[i][0] = p[0];
                af[i][1] = p[8 * SSTR];
                af[i][2] = p[4];
                af[i][3] = p[8 * SSTR + 4];
            }
            uint32_t bf[4][2];
            #pragma unroll
            for (int j = 0; j < 4; ++j) {
                const uint32_t* p = &sB[(wn + j*8 + qrow) * SSTR + kbase];
                bf[j][0] = p[0];
                bf[j][1] = p[4];
            }
            #pragma unroll
            for (int i = 0; i < 4; ++i)
                #pragma unroll
                for (int j = 0; j < 4; ++j)
                    mma_tf32(acc[i*4 + j],
                             af[i][0], af[i][1], af[i][2], af[i][3],
                             bf[j][0], bf[j][1]);
        }
    }

    #pragma unroll
    for (int i = 0; i < 4; ++i) {
        #pragma unroll
        for (int j = 0; j < 4; ++j) {
            const float* a4 = acc[i*4 + j];
            const int colg  = n0 + wn + j*8 + 2*qcol;
            const float2 bv = *reinterpret_cast<const float2*>(bias + colg);
            #pragma unroll
            for (int half = 0; half < 2; ++half) {
                const int m = m0 + wm + i*16 + qrow + half*8;
                float2 o;
                o.x = a4[half*2 + 0] + bv.x;
                o.y = a4[half*2 + 1] + bv.y;
                size_t idx;
                if (SCATTER) {
                    const int b = m >> 11;
                    const int s = m & (NS - 1);
                    const int h = colg >> 6;
                    const int hd = colg & 63;
                    idx = (((size_t)(b*NH + h))*NS + s)*NHD + hd;
                } else {
                    idx = (size_t)m * N + colg;
                }
                *reinterpret_cast<float2*>(C + idx) = o;
            }
        }
    }
}

// ---------------------------------------------------------------------------
// Tensor-core flash attention (tf32 mma.sync), causal.
// R10: P fragment relayout via intra-quad shuffles (no smem P buffer),
// double-buffered K/V tiles -> ONE __syncthreads per key-tile iteration.
// Numerics bit-identical to R7/R9 (same values, same accumulation order).
// smem: 26112 words = 104448 B (occ 2).
// ---------------------------------------------------------------------------
#define AQ_STR   68
#define OFF_Q    0              // 128*68 = 8704
#define OFF_K0   8704           // 64*68  = 4352
#define OFF_K1   13056
#define OFF_V0   17408
#define OFF_V1   21760
#define SMEM_WORDS 26112        // *4 = 104448 B

__global__ void __launch_bounds__(256, 2)
attn_tc(const float* __restrict__ Q, const float* __restrict__ K,
        const float* __restrict__ V, float* __restrict__ O)
{
    extern __shared__ uint32_t sm[];
    uint32_t* sQ = sm + OFF_Q;

    const int tid  = threadIdx.x;
    const int wid  = tid >> 5;
    const int lane = tid & 31;
    const int qrow = lane >> 2;   // 0..7
    const int qcol = lane & 3;    // 0..3
    const int wm   = wid * 16;

    const int qt = (NS/128 - 1) - blockIdx.x;   // largest-work tiles first
    const int h  = blockIdx.y;
    const int b  = blockIdx.z;
    const int bh = b*NH + h;

    const float* Qb = Q + (size_t)bh * NS * NHD;
    const float* Kb = K + (size_t)bh * NS * NHD;
    const float* Vb = V + (size_t)bh * NS * NHD;

    const int kr = tid >> 4;         // 0..15
    const int kc = (tid & 15) * 4;   // 0..60
    const int vkey = tid & 63;
    const int vdg  = (tid >> 6) * 16;

    // ---- load Q tile as tf32, [row][d] ----
    #pragma unroll
    for (int p = 0; p < 8; ++p) {
        int lin = tid + 256*p;
        int r = lin >> 4, c = (lin & 15) * 4;
        float4 qv = *reinterpret_cast<const float4*>(
            Qb + (size_t)(qt*128 + r)*NHD + c);
        uint32_t* d = &sQ[r * AQ_STR + c];
        d[0] = cvt_tf32(qv.x);
        d[1] = cvt_tf32(qv.y);
        d[2] = cvt_tf32(qv.z);
        d[3] = cvt_tf32(qv.w);
    }

    float o[8][4];
    #pragma unroll
    for (int nt = 0; nt < 8; ++nt)
        #pragma unroll
        for (int e = 0; e < 4; ++e) o[nt][e] = 0.f;
    float mrow[2] = {-1e30f, -1e30f};
    float lrow[2] = {0.f, 0.f};

    const int jmax = 2*qt + 1;

    float4 kreg[4], vreg[4];
    auto ldg_tile = [&](int jj) {
        const size_t rb = (size_t)jj * 64;
        #pragma unroll
        for (int p = 0; p < 4; ++p)
            kreg[p] = *reinterpret_cast<const float4*>(
                Kb + (rb + kr + p*16)*NHD + kc);
        #pragma unroll
        for (int g = 0; g < 4; ++g)
            vreg[g] = *reinterpret_cast<const float4*>(
                Vb + (rb + vkey)*NHD + vdg + g*4);
    };
    auto sts_tile = [&](int buf) {
        uint32_t* sK  = sm + OFF_K0 + buf * 4352;
        uint32_t* sVt = sm + OFF_V0 + buf * 4352;
        #pragma unroll
        for (int p = 0; p < 4; ++p) {
            uint4 t;
            t.x = cvt_tf32(kreg[p].x);
            t.y = cvt_tf32(kreg[p].y);
            t.z = cvt_tf32(kreg[p].z);
            t.w = cvt_tf32(kreg[p].w);
            *reinterpret_cast<uint4*>(&sK[(kr + p*16) * AQ_STR + kc]) = t;
        }
        #pragma unroll
        for (int g = 0; g < 4; ++g) {
            float f[4] = {vreg[g].x, vreg[g].y, vreg[g].z, vreg[g].w};
            #pragma unroll
            for (int e = 0; e < 4; ++e)
                sVt[(vdg + g*4 + e) * AQ_STR + vkey] = cvt_tf32(f[e]);
        }
    };

    // ---- prologue: tile 0 staged, tile 1 in regs ----
    ldg_tile(0);
    sts_tile(0);
    ldg_tile(1);          // jmax >= 1 always
    __syncthreads();      // Q + buf0 ready

    const int src1 = qrow*4 + (qcol >> 1);   // P-shuffle source lanes
    const int src2 = src1 + 2;
    const bool esel = (qcol & 1);

    for (int j = 0; j <= jmax; ++j) {
        const uint32_t* sK  = sm + OFF_K0 + (j & 1) * 4352;
        const uint32_t* sVt = sm + OFF_V0 + (j & 1) * 4352;

        // stage tile j+1 into the other buffer (overlaps compute below)
        if (j < jmax) {
            sts_tile((j + 1) & 1);
            if (j + 1 < jmax) ldg_tile(j + 2);
        }

        const bool active = (j*64 <= qt*128 + wm + 15);
        if (active) {
            // ---- S = Q @ K^T ----
            float s[8][4];
            #pragma unroll
            for (int nt = 0; nt < 8; ++nt)
                #pragma unroll
                for (int e = 0; e < 4; ++e) s[nt][e] = 0.f;

            #pragma unroll
            for (int ks = 0; ks < 8; ++ks) {
                const uint32_t* qp = &sQ[(wm + qrow) * AQ_STR + ks*8 + qcol];
                uint32_t a0 = qp[0], a1 = qp[8*AQ_STR], a2 = qp[4], a3 = qp[8*AQ_STR + 4];
                #pragma unroll
                for (int nt = 0; nt < 8; ++nt) {
                    const int off = (nt*8 + qrow) * AQ_STR + ks*8 + qcol;
                    mma_tf32(s[nt], a0, a1, a2, a3, sK[off], sK[off + 4]);
                }
            }

            // ---- online softmax (per lane: 2 rows) ----
            const bool need_mask = (j >= 2*qt);
            #pragma unroll
            for (int r = 0; r < 2; ++r) {
                const int rowg = qt*128 + wm + qrow + r*8;
                float mx = -1e30f;
                #pragma unroll
                for (int nt = 0; nt < 8; ++nt) {
                    const int colg = j*64 + nt*8 + 2*qcol;
                    float v0 = s[nt][r*2 + 0] * SCALE_F;
                    float v1 = s[nt][r*2 + 1] * SCALE_F;
                    if (need_mask) {
                        if (colg     > rowg) v0 = -1e30f;
                        if (colg + 1 > rowg) v1 = -1e30f;
                    }
                    s[nt][r*2 + 0] = v0;
                    s[nt][r*2 + 1] = v1;
                    mx = fmaxf(mx, fmaxf(v0, v1));
                }
                mx = fmaxf(mx, __shfl_xor_sync(0xffffffffu, mx, 1));
                mx = fmaxf(mx, __shfl_xor_sync(0xffffffffu, mx, 2));
                const float mn    = fmaxf(mrow[r], mx);
                const float alpha = __expf(mrow[r] - mn);
                mrow[r] = mn;
                float ls = 0.f;
                #pragma unroll
                for (int nt = 0; nt < 8; ++nt) {
                    float p0 = __expf(s[nt][r*2 + 0] - mn);
                    float p1 = __expf(s[nt][r*2 + 1] - mn);
                    s[nt][r*2 + 0] = p0;
                    s[nt][r*2 + 1] = p1;
                    ls += p0 + p1;
                }
                ls += __shfl_xor_sync(0xffffffffu, ls, 1);
                ls += __shfl_xor_sync(0xffffffffu, ls, 2);
                lrow[r] = lrow[r]*alpha + ls;
                #pragma unroll
                for (int nt = 0; nt < 8; ++nt) {
                    o[nt][r*2 + 0] *= alpha;
                    o[nt][r*2 + 1] *= alpha;
                }
            }

            // ---- O += P @ V; A-fragment built via intra-quad shuffles ----
            // s[ks] holds this lane's C-fragment of P tile ks (keys ks*8..+7):
            //   s[ks][0]=P[qrow][ks*8+2qc], [1]=+1, [2]=P[qrow+8][..], [3]=+1
            // A-frag needs P[qrow][ks*8+qcol] etc. -> lanes src1/src2.
            #pragma unroll
            for (int ks = 0; ks < 8; ++ks) {
                uint32_t v0 = cvt_tf32(s[ks][0]);
                uint32_t v1 = cvt_tf32(s[ks][1]);
                uint32_t v2 = cvt_tf32(s[ks][2]);
                uint32_t v3 = cvt_tf32(s[ks][3]);
                uint32_t x0 = __shfl_sync(0xffffffffu, v0, src1);
                uint32_t x1 = __shfl_sync(0xffffffffu, v1, src1);
                uint32_t x2 = __shfl_sync(0xffffffffu, v2, src1);
                uint32_t x3 = __shfl_sync(0xffffffffu, v3, src1);
                uint32_t y0 = __shfl_sync(0xffffffffu, v0, src2);
                uint32_t y1 = __shfl_sync(0xffffffffu, v1, src2);
                uint32_t y2 = __shfl_sync(0xffffffffu, v2, src2);
                uint32_t y3 = __shfl_sync(0xffffffffu, v3, src2);
                uint32_t a0 = esel ? x1 : x0;
                uint32_t a1 = esel ? x3 : x2;
                uint32_t a2 = esel ? y1 : y0;
                uint32_t a3 = esel ? y3 : y2;
                #pragma unroll
                for (int nt = 0; nt < 8; ++nt) {
                    const int off = (nt*8 + qrow) * AQ_STR + ks*8 + qcol;
                    mma_tf32(o[nt], a0, a1, a2, a3, sVt[off], sVt[off + 4]);
                }
            }
        }

        __syncthreads();   // compute(j) done AND STS(j+1) done
    }

    // ---- normalize + write [B,S,D] ----
    #pragma unroll
    for (int r = 0; r < 2; ++r) {
        const float inv = 1.0f / lrow[r];
        const int rowg = qt*128 + wm + qrow + r*8;
        #pragma unroll
        for (int nt = 0; nt < 8; ++nt) {
            const int col = h*NHD + nt*8 + 2*qcol;
            float2 ov;
            ov.x = o[nt][r*2 + 0] * inv;
            ov.y = o[nt][r*2 + 1] * inv;
            *reinterpret_cast<float2*>(
                O + ((size_t)b*NS + rowg)*ND + col) = ov;
        }
    }
}

// ---------------------------------------------------------------------------
extern "C" void kernel_launch(void* const* d_in, const int* in_sizes, int n_in,
                              void* d_out, int out_size)
{
    const float* x  = (const float*)d_in[0];
    const float* wq = (const float*)d_in[1];
    const float* bq = (const float*)d_in[2];
    const float* wk = (const float*)d_in[3];
    const float* bk = (const float*)d_in[4];
    const float* wv = (const float*)d_in[5];
    const float* bv = (const float*)d_in[6];
    const float* wo = (const float*)d_in[7];
    const float* bo = (const float*)d_in[8];
    float* out = (float*)d_out;

    float *q, *k, *v, *att;
    cudaGetSymbolAddress((void**)&q,   g_q);
    cudaGetSymbolAddress((void**)&k,   g_k);
    cudaGetSymbolAddress((void**)&v,   g_v);
    cudaGetSymbolAddress((void**)&att, g_att);

    static bool attr_done = false;
    if (!attr_done) {
        cudaFuncSetAttribute(attn_tc,
            cudaFuncAttributeMaxDynamicSharedMemorySize, SMEM_WORDS * 4);
        attr_done = true;
    }

    // Fused QKV projection (R9, measured-fast)
    dim3 qkv_grid(ND/128, NM/128, 3);   // (8, 32, 3) = 768 CTAs
    gemm_tc<true><<<qkv_grid, 256>>>(
        x, wq, bq, q, wk, bk, k, wv, bv, v);

    dim3 agrid(NS/128, NH, NB);         // (16, 16, 2)
    attn_tc<<<agrid, 256, SMEM_WORDS * 4>>>(q, k, v, att);

    // Output projection (z=1)
    dim3 ogrid(ND/128, NM/128, 1);
    gemm_tc<false><<<ogrid, 256>>>(
        att, wo, bo, out, wo, bo, out, wo, bo, out);
}